// round 11
// baseline (speedup 1.0000x reference)
#include <cuda_runtime.h>

// ---------------------------------------------------------------------------
// EntropyPool: x (32,128,160,64) f32, values = round(g*10)/10, g~N(0,1) f32.
// bin = rint(v*10)+64 in ~[9,119] (128 bins, clamped). argmin over the 2x2
// window of -p log p == argmin of global count (p << 1/e), first index wins
// ties. Value reconstructed as (bin-64)*0.1f (<=1 ulp vs reference).
//
// Pass 1 (hist): 128-bin histogram, per-warp-lane private u8x4-packed
//   counters (4KB/warp, bank==lane conflict-free, no atomics); writes packed
//   bin bytes to g_keys4 (streaming __ldcs input keeps keys L2-resident).
// Pass 2: reduce partials -> g_cnt4[bin] = count<<2 (pool-ready keys).
// Pass 3 (pool): replicated conflict-free count LUT tbl[bin][lane]; key =
//   (count<<2)+pos, min-tree select, arithmetic value reconstruction.
// ---------------------------------------------------------------------------

#define HIST_BLOCKS  1628            // 148 SMs * 11 resident blocks
#define HIST_THREADS 128             // 4 warps/block -> 44 warps/SM
#define OUT4_TOTAL   2621440u        // 10,485,760 out floats / 4
#define KEY_BASE     (0x4B400000 - 64)

__device__ unsigned g_partial[HIST_BLOCKS * 128];
__device__ unsigned g_cnt4[128];               // count << 2
__device__ unsigned g_keys4[10485760];         // one byte-bin per float

// bin = rint(v*10) + 64 via FFMA magic-number RNE; one unsigned min clamps
// both (impossible) tails.
__device__ __forceinline__ unsigned binof(float v) {
    int k = __float_as_int(fmaf(v, 10.0f, 12582912.0f)) - KEY_BASE;
    return min((unsigned)k, 127u);
}

// ---------------- Pass 1: histogram + key emission ------------------------
__global__ void __launch_bounds__(HIST_THREADS, 11) hist_kernel(
        const float4* __restrict__ x, unsigned n4) {
    // [warp][word][lane]; u32 word = 4 u8 counters. Bank = lane: conflict-free.
    __shared__ unsigned h[4][32][32];
    const int tid  = threadIdx.x;
    const int wid  = tid >> 5;
    const int lane = tid & 31;

    for (int i = tid; i < 4 * 32 * 32; i += HIST_THREADS)
        ((unsigned*)h)[i] = 0u;
    __syncthreads();

    unsigned* hw = &h[wid][0][0];

    const unsigned stride = HIST_BLOCKS * HIST_THREADS;
    unsigned i = blockIdx.x * HIST_THREADS + (unsigned)tid;

    // 4 streaming float4 loads per iteration (MLP=4, L2 evict-first so the
    // key array stays resident); each float4 is one 4-element RMW group with
    // duplicate correction (C aliasing rules keep the RMWs ordered).
    for (; i + 3u * stride < n4; i += 4u * stride) {
        float4 v[4];
        v[0] = __ldcs(&x[i]);
        v[1] = __ldcs(&x[i + stride]);
        v[2] = __ldcs(&x[i + 2u * stride]);
        v[3] = __ldcs(&x[i + 3u * stride]);
        #pragma unroll
        for (int g = 0; g < 4; g++) {
            const float f[4] = { v[g].x, v[g].y, v[g].z, v[g].w };
            unsigned kb[4], wd[4], inc[4], c[4];
            #pragma unroll
            for (int j = 0; j < 4; j++) {
                kb[j]  = binof(f[j]);
                wd[j]  = kb[j] >> 2;
                inc[j] = 1u << ((kb[j] & 3u) << 3);
                c[j]   = hw[wd[j] * 32 + lane];
            }
            #pragma unroll
            for (int j = 1; j < 4; j++)
                #pragma unroll
                for (int q = 0; q < j; q++)
                    if (wd[q] == wd[j]) c[j] += inc[q];
            #pragma unroll
            for (int j = 0; j < 4; j++)
                hw[wd[j] * 32 + lane] = c[j] + inc[j];
            g_keys4[i + g * stride] =
                kb[0] | (kb[1] << 8) | (kb[2] << 16) | (kb[3] << 24);
        }
    }
    // Tail: one float4 at a time.
    for (; i < n4; i += stride) {
        float4 v = __ldcs(&x[i]);
        const float f[4] = { v.x, v.y, v.z, v.w };
        unsigned kb[4], wd[4], inc[4], c[4];
        #pragma unroll
        for (int j = 0; j < 4; j++) {
            kb[j]  = binof(f[j]);
            wd[j]  = kb[j] >> 2;
            inc[j] = 1u << ((kb[j] & 3u) << 3);
            c[j]   = hw[wd[j] * 32 + lane];
        }
        #pragma unroll
        for (int j = 1; j < 4; j++)
            #pragma unroll
            for (int q = 0; q < j; q++)
                if (wd[q] == wd[j]) c[j] += inc[q];
        #pragma unroll
        for (int j = 0; j < 4; j++)
            hw[wd[j] * 32 + lane] = c[j] + inc[j];
        g_keys4[i] = kb[0] | (kb[1] << 8) | (kb[2] << 16) | (kb[3] << 24);
    }
    __syncthreads();

    // Flush per-block partials (128 bins), lane-rotated conflict-free reads.
    if (tid < 128) {
        const int word = tid >> 2;
        const int sh   = (tid & 3) << 3;
        unsigned s = 0;
        #pragma unroll 4
        for (int j = 0; j < 32; j++) {
            const int l = (j + tid) & 31;
            #pragma unroll
            for (int ww = 0; ww < 4; ww++)
                s += (h[ww][word][l] >> sh) & 0xFFu;
        }
        g_partial[blockIdx.x * 128u + tid] = s;
    }
}

// ---------------- Pass 2: reduce partials -> count<<2 ---------------------
__global__ void __launch_bounds__(256) reduce_kernel() {
    __shared__ unsigned s[256];
    const int bin = blockIdx.x;          // 128 blocks
    const int t = threadIdx.x;
    unsigned acc = 0;
    for (int b = t; b < HIST_BLOCKS; b += 256)
        acc += g_partial[b * 128 + bin];
    s[t] = acc;
    __syncthreads();
    #pragma unroll
    for (int o = 128; o > 0; o >>= 1) {
        if (t < o) s[t] += s[t + o];
        __syncthreads();
    }
    if (t == 0) g_cnt4[bin] = s[0] << 2;   // room for 2-bit position
}

// ---------------- Pass 3: pooling from keys -------------------------------
__global__ void __launch_bounds__(256) pool_kernel(float4* __restrict__ out) {
    // Replicated count LUT: tbl[bin*32 + lane] -> bank = lane, conflict-free
    // for arbitrary per-lane bins.
    __shared__ unsigned tbl[128 * 32];
    const int t    = threadIdx.x;
    const int lane = t & 31;
    #pragma unroll
    for (int e = t; e < 128 * 32; e += 256)
        tbl[e] = g_cnt4[e >> 5];
    __syncthreads();

    const unsigned gid  = blockIdx.x * 256u + (unsigned)t;  // grid exact
    const unsigned c4   = gid & 15u;                 // float4 index in C=64
    const unsigned spat = gid >> 4;                  // (n*64+oh)*80 + ow
    const unsigned ow   = spat % 80u;
    const unsigned rest = spat / 80u;
    const unsigned oh   = rest & 63u;
    const unsigned n    = rest >> 6;

    const unsigned row = n * 128u + oh * 2u;
    const unsigned b00 = (row * 160u + ow * 2u) * 16u + c4;

    // 4 key words = 4 channels x 4 window positions (read-once streaming).
    const unsigned k0 = __ldcs(&g_keys4[b00]);           // (2oh,   2ow)
    const unsigned k1 = __ldcs(&g_keys4[b00 + 16u]);     // (2oh,   2ow+1)
    const unsigned k2 = __ldcs(&g_keys4[b00 + 2560u]);   // (2oh+1, 2ow)
    const unsigned k3 = __ldcs(&g_keys4[b00 + 2576u]);   // (2oh+1, 2ow+1)

    float4 r;
    float* rr = (float*)&r;
    #pragma unroll
    for (int c = 0; c < 4; c++) {
        // byte c of each key word, zero-extended: single PRMT each
        const unsigned b0 = __byte_perm(k0, 0u, 0x4440 + c);
        const unsigned b1 = __byte_perm(k1, 0u, 0x4440 + c);
        const unsigned b2 = __byte_perm(k2, 0u, 0x4440 + c);
        const unsigned b3 = __byte_perm(k3, 0u, 0x4440 + c);
        // key = (count<<2) + pos: lexicographic (count, pos) -> strict
        // first-index tie-break, matching jnp.argmin
        const unsigned e0 = tbl[(b0 << 5) | lane];
        const unsigned e1 = tbl[(b1 << 5) | lane] + 1u;
        const unsigned e2 = tbl[(b2 << 5) | lane] + 2u;
        const unsigned e3 = tbl[(b3 << 5) | lane] + 3u;
        const unsigned m  = min(min(e0, e1), min(e2, e3));
        const unsigned pos = m & 3u;
        const unsigned bin = pos == 0u ? b0 : pos == 1u ? b1
                           : pos == 2u ? b2 : b3;
        rr[c] = (float)((int)bin - 64) * 0.1f;
    }
    out[gid] = r;
}

// ---------------------------------------------------------------------------
extern "C" void kernel_launch(void* const* d_in, const int* in_sizes, int n_in,
                              void* d_out, int out_size) {
    (void)n_in; (void)out_size;
    const float4* x4 = (const float4*)d_in[0];
    const unsigned n4 = (unsigned)(in_sizes[0] >> 2);

    hist_kernel<<<HIST_BLOCKS, HIST_THREADS>>>(x4, n4);
    reduce_kernel<<<128, 256>>>();
    pool_kernel<<<OUT4_TOTAL / 256u, 256>>>((float4*)d_out);
}

// round 12
// speedup vs baseline: 1.0703x; 1.0703x over previous
#include <cuda_runtime.h>

// ---------------------------------------------------------------------------
// EntropyPool: x (32,128,160,64) f32, values = round(g*10)/10, g~N(0,1) f32
// (bounded, so bin = rint(v*10)+64 in [8,120]). argmin over the 2x2 window of
// -p log p == argmin of global count (p << 1/e), first index wins ties.
// Value reconstructed as (bin-64)*0.1f (bit-matching, rel_err 0 measured).
//
// Pass 0: zero g_cnt4.
// Pass 1 (hist): fma.rn.f32x2 magic-number binning (low byte of the packed
//   FFMA result IS the bin), per-warp-lane private u8x4-packed counters
//   (4KB/warp, bank==lane, no atomics, no conflicts), 4-elem RMW groups with
//   duplicate correction; PRMT-packed bin bytes written to g_keys4.
// Pass 2 (reduce): coalesced row reads of g_partial + atomicAdd into
//   g_cnt4[bin] = count<<2.
// Pass 3 (pool): replicated conflict-free count LUT tbl[bin][lane];
//   key = (count<<2)+pos, min-tree select, first-index tie-break.
// ---------------------------------------------------------------------------

#define HIST_BLOCKS  1480            // 148 SMs * 10 resident blocks
#define HIST_THREADS 128             // 4 warps/block -> 40 warps/SM
#define OUT4_TOTAL   2621440u        // 10,485,760 out floats / 4
#define RED_BLOCKS   37              // 1480 rows = 37 * 40
#define ROWS_PER_RED 40

__device__ unsigned g_partial[HIST_BLOCKS * 128];
__device__ unsigned g_cnt4[128];               // count << 2
__device__ unsigned g_keys4[10485760];         // one byte-bin per float

// Packed binning: fma.rn.f32x2(v, {10,10}, {12582976,12582976}).
// 12582976 = 1.5*2^23 + 64: unit mantissa spacing => RNE to integer; the
// low byte of each 32-bit half equals rint(v*10)+64 = bin (in [8,120],
// byte1 stays 0, no carry). Identical rounding to scalar fmaf.
__device__ __forceinline__ unsigned long long fma2bin(unsigned long long v) {
    unsigned long long r;
    asm("fma.rn.f32x2 %0, %1, %2, %3;"
        : "=l"(r)
        : "l"(v), "l"(0x4120000041200000ULL), "l"(0x4B4000404B400040ULL));
    return r;
}

// ---------------- Pass 0: zero the atomic accumulator ---------------------
__global__ void zero_kernel() { g_cnt4[threadIdx.x] = 0u; }

// ---------------- Pass 1: histogram + key emission ------------------------
__global__ void __launch_bounds__(HIST_THREADS, 10) hist_kernel(
        const float4* __restrict__ x, unsigned n4) {
    // [warp][word][lane]; u32 word = 4 u8 counters (bins 4w..4w+3).
    // Address = word*128 + lane*4 -> bank = lane -> conflict-free.
    __shared__ unsigned h[4][32][32];
    const int tid  = threadIdx.x;
    const int wid  = tid >> 5;
    const int lane = tid & 31;

    for (int i = tid; i < 4 * 32 * 32; i += HIST_THREADS)
        ((unsigned*)h)[i] = 0u;
    __syncthreads();

    unsigned* hw = &h[wid][0][lane];   // + (bin&0x7C)<<3 selects the word

    const unsigned stride = HIST_BLOCKS * HIST_THREADS;
    unsigned i = blockIdx.x * HIST_THREADS + (unsigned)tid;

    union F4U { float4 f; unsigned long long u[2]; };

    // 4 float4 loads per iteration (MLP=4); each float4 is one 4-element
    // RMW group with duplicate correction (C aliasing keeps groups ordered).
    for (; i + 3u * stride < n4; i += 4u * stride) {
        F4U v[4];
        v[0].f = x[i];
        v[1].f = x[i + stride];
        v[2].f = x[i + 2u * stride];
        v[3].f = x[i + 3u * stride];
        #pragma unroll
        for (int g = 0; g < 4; g++) {
            const unsigned long long r0 = fma2bin(v[g].u[0]);
            const unsigned long long r1 = fma2bin(v[g].u[1]);
            const unsigned b[4] = { (unsigned)r0, (unsigned)(r0 >> 32),
                                    (unsigned)r1, (unsigned)(r1 >> 32) };
            unsigned wo[4], inc[4], c[4];
            #pragma unroll
            for (int j = 0; j < 4; j++) {
                wo[j]  = (b[j] & 0x7Cu) << 3;          // word*32 (u32 index)
                inc[j] = 1u << ((b[j] & 3u) << 3);
                c[j]   = hw[wo[j]];
            }
            #pragma unroll
            for (int j = 1; j < 4; j++)
                #pragma unroll
                for (int q = 0; q < j; q++)
                    if (wo[q] == wo[j]) c[j] += inc[q];
            #pragma unroll
            for (int j = 0; j < 4; j++)
                hw[wo[j]] = c[j] + inc[j];
            g_keys4[i + g * stride] =
                __byte_perm(__byte_perm(b[0], b[1], 0x0040),
                            __byte_perm(b[2], b[3], 0x0040), 0x5410);
        }
    }
    // Tail: one float4 at a time.
    for (; i < n4; i += stride) {
        F4U v; v.f = x[i];
        const unsigned long long r0 = fma2bin(v.u[0]);
        const unsigned long long r1 = fma2bin(v.u[1]);
        const unsigned b[4] = { (unsigned)r0, (unsigned)(r0 >> 32),
                                (unsigned)r1, (unsigned)(r1 >> 32) };
        unsigned wo[4], inc[4], c[4];
        #pragma unroll
        for (int j = 0; j < 4; j++) {
            wo[j]  = (b[j] & 0x7Cu) << 3;
            inc[j] = 1u << ((b[j] & 3u) << 3);
            c[j]   = hw[wo[j]];
        }
        #pragma unroll
        for (int j = 1; j < 4; j++)
            #pragma unroll
            for (int q = 0; q < j; q++)
                if (wo[q] == wo[j]) c[j] += inc[q];
        #pragma unroll
        for (int j = 0; j < 4; j++)
            hw[wo[j]] = c[j] + inc[j];
        g_keys4[i] = __byte_perm(__byte_perm(b[0], b[1], 0x0040),
                                 __byte_perm(b[2], b[3], 0x0040), 0x5410);
    }
    __syncthreads();

    // Flush per-block partials (128 bins), lane-rotated conflict-free reads.
    if (tid < 128) {
        const int word = tid >> 2;
        const int sh   = (tid & 3) << 3;
        unsigned s = 0;
        #pragma unroll 4
        for (int j = 0; j < 32; j++) {
            const int l = (j + tid) & 31;
            #pragma unroll
            for (int ww = 0; ww < 4; ww++)
                s += (h[ww][word][l] >> sh) & 0xFFu;
        }
        g_partial[blockIdx.x * 128u + tid] = s;
    }
}

// ---------------- Pass 2: coalesced reduce + atomics ----------------------
// Block b sums rows [b*40, b*40+40) of g_partial (each row = 128 u32,
// coalesced 512B line per 128 threads; thread t covers bin t&127, sub-row
// t>>7). 37*128 atomicAdds (37 per bin address) finish it.
__global__ void __launch_bounds__(256) reduce_kernel() {
    __shared__ unsigned s[256];
    const int t   = threadIdx.x;
    const int col = t & 127;
    const int sub = t >> 7;                  // 0 or 1
    const unsigned base = blockIdx.x * ROWS_PER_RED;
    unsigned acc = 0;
    #pragma unroll
    for (int k = 0; k < ROWS_PER_RED / 2; k++)
        acc += g_partial[(base + 2u * k + sub) * 128u + col];
    s[t] = acc;
    __syncthreads();
    if (t < 128)
        atomicAdd(&g_cnt4[t], (s[t] + s[t + 128]) << 2); // count<<2
}

// ---------------- Pass 3: pooling from keys -------------------------------
__global__ void __launch_bounds__(256) pool_kernel(float4* __restrict__ out) {
    // Replicated count LUT: tbl[bin*32 + lane] -> bank = lane, conflict-free
    // for arbitrary per-lane bins.
    __shared__ unsigned tbl[128 * 32];
    const int t    = threadIdx.x;
    const int lane = t & 31;
    #pragma unroll
    for (int e = t; e < 128 * 32; e += 256)
        tbl[e] = g_cnt4[e >> 5];
    __syncthreads();

    const unsigned gid  = blockIdx.x * 256u + (unsigned)t;  // grid exact
    const unsigned c4   = gid & 15u;                 // float4 index in C=64
    const unsigned spat = gid >> 4;                  // (n*64+oh)*80 + ow
    const unsigned ow   = spat % 80u;
    const unsigned rest = spat / 80u;
    const unsigned oh   = rest & 63u;
    const unsigned n    = rest >> 6;

    const unsigned row = n * 128u + oh * 2u;
    const unsigned b00 = (row * 160u + ow * 2u) * 16u + c4;

    // 4 key words = 4 channels x 4 window positions.
    const unsigned k0 = g_keys4[b00];           // (2oh,   2ow)
    const unsigned k1 = g_keys4[b00 + 16u];     // (2oh,   2ow+1)
    const unsigned k2 = g_keys4[b00 + 2560u];   // (2oh+1, 2ow)
    const unsigned k3 = g_keys4[b00 + 2576u];   // (2oh+1, 2ow+1)

    float4 r;
    float* rr = (float*)&r;
    #pragma unroll
    for (int c = 0; c < 4; c++) {
        // byte c of each key word, zero-extended: single PRMT each
        const unsigned b0 = __byte_perm(k0, 0u, 0x4440 + c);
        const unsigned b1 = __byte_perm(k1, 0u, 0x4440 + c);
        const unsigned b2 = __byte_perm(k2, 0u, 0x4440 + c);
        const unsigned b3 = __byte_perm(k3, 0u, 0x4440 + c);
        // key = (count<<2) + pos: lexicographic (count,pos) -> strict
        // first-index tie-break, matching jnp.argmin
        const unsigned e0 = tbl[(b0 << 5) | lane];
        const unsigned e1 = tbl[(b1 << 5) | lane] + 1u;
        const unsigned e2 = tbl[(b2 << 5) | lane] + 2u;
        const unsigned e3 = tbl[(b3 << 5) | lane] + 3u;
        const unsigned m  = min(min(e0, e1), min(e2, e3));
        const unsigned pos = m & 3u;
        const unsigned bin = pos == 0u ? b0 : pos == 1u ? b1
                           : pos == 2u ? b2 : b3;
        rr[c] = (float)((int)bin - 64) * 0.1f;
    }
    out[gid] = r;
}

// ---------------------------------------------------------------------------
extern "C" void kernel_launch(void* const* d_in, const int* in_sizes, int n_in,
                              void* d_out, int out_size) {
    (void)n_in; (void)out_size;
    const float4* x4 = (const float4*)d_in[0];
    const unsigned n4 = (unsigned)(in_sizes[0] >> 2);

    zero_kernel<<<1, 128>>>();
    hist_kernel<<<HIST_BLOCKS, HIST_THREADS>>>(x4, n4);
    reduce_kernel<<<RED_BLOCKS, 256>>>();
    pool_kernel<<<OUT4_TOTAL / 256u, 256>>>((float4*)d_out);
}